// round 16
// baseline (speedup 1.0000x reference)
#include <cuda_runtime.h>
#include <cuda_bf16.h>
#include <cstdint>

// ---------------- problem dims ----------------
#define CC   2048
#define KTT  64
#define DD   1024
#define DE   128
#define DF   256
#define NH   8
#define DHH  128
#define DX   1152   // D + De
#define PHH  1024
#define KQM  1408   // D + Df + De  (merged Q/gate1 GEMM K)

// ---------------- scratch (__device__ globals; no allocations) ----------------
__device__ __align__(128) __nv_bfloat16 g_Wc[2048 * KQM];        // [W2|b*Wf|0 ; g1w_D|0|g1w_De]
__device__ __align__(128) __nv_bfloat16 g_wfm[CC * KQM];         // [w | fC | mean(Et)]
__device__ __align__(128) __nv_bfloat16 g_QH[CC * 2048];         // [Q | hmid]
__device__ __align__(128) __nv_bfloat16 g_W1t[NH * DX * DHH];    // [h][x][d]
__device__ __align__(128) __nv_bfloat16 g_Wvb[DD * DX];
__device__ __align__(128) __nv_bfloat16 g_g2wb[DD * PHH];
__device__ __align__(128) __nv_bfloat16 g_qt[(size_t)CC * NH * DX];
__device__ __align__(128) __nv_bfloat16 g_Z[(size_t)CC * NH * DX];
__device__ __align__(128) float g_g[CC * DD];
__device__ __align__(128) float g_U[CC * DD];

// ---------------- PTX helpers ----------------
__device__ __forceinline__ void cpasync16(void* dst, const void* src) {
    uint32_t d = (uint32_t)__cvta_generic_to_shared(dst);
    asm volatile("cp.async.cg.shared.global [%0], [%1], 16;\n" :: "r"(d), "l"(src));
}
__device__ __forceinline__ void cp_commit() {
    asm volatile("cp.async.commit_group;\n" ::: "memory");
}
template <int N>
__device__ __forceinline__ void cp_wait() {
    asm volatile("cp.async.wait_group %0;\n" :: "n"(N) : "memory");
}
__device__ __forceinline__ void ldm_x4(uint32_t* r, const void* p) {
    uint32_t a = (uint32_t)__cvta_generic_to_shared(p);
    asm volatile("ldmatrix.sync.aligned.m8n8.x4.shared.b16 {%0,%1,%2,%3}, [%4];\n"
                 : "=r"(r[0]), "=r"(r[1]), "=r"(r[2]), "=r"(r[3]) : "r"(a));
}
__device__ __forceinline__ void ldm_x4t(uint32_t* r, const void* p) {
    uint32_t a = (uint32_t)__cvta_generic_to_shared(p);
    asm volatile("ldmatrix.sync.aligned.m8n8.x4.trans.shared.b16 {%0,%1,%2,%3}, [%4];\n"
                 : "=r"(r[0]), "=r"(r[1]), "=r"(r[2]), "=r"(r[3]) : "r"(a));
}
__device__ __forceinline__ void mma16816(float* c, const uint32_t* a, uint32_t b0, uint32_t b1) {
    asm volatile(
        "mma.sync.aligned.m16n8k16.row.col.f32.bf16.bf16.f32 "
        "{%0,%1,%2,%3},{%4,%5,%6,%7},{%8,%9},{%0,%1,%2,%3};\n"
        : "+f"(c[0]), "+f"(c[1]), "+f"(c[2]), "+f"(c[3])
        : "r"(a[0]), "r"(a[1]), "r"(a[2]), "r"(a[3]), "r"(b0), "r"(b1));
}
__device__ __forceinline__ uint32_t packbf2(float a, float b) {
    __nv_bfloat162 t = __floats2bfloat162_rn(a, b);
    return *(uint32_t*)&t;
}
__device__ __forceinline__ void prefetchL2(const void* p) {
    asm volatile("prefetch.global.L2 [%0];" :: "l"(p));
}
__device__ __forceinline__ void gdc_wait() {
    asm volatile("griddepcontrol.wait;" ::: "memory");
}

// ---------------- fat prep kernel ----------------
#define N_WC  (2048 * 352)
#define N_WFM (2048 * 352)
#define N_G2  (1024 * 1024 / 4)
#define N_WV  (1024 * 1152 / 4)
#define N_W1T (8 * 1152 * 128)
#define PREP_TOTAL (N_WC + N_WFM + N_G2 + N_WV + N_W1T)

__global__ void __launch_bounds__(256)
prep_fat_k(const float* __restrict__ w, const float* __restrict__ Et,
           const float* __restrict__ fC, const float* __restrict__ W1,
           const float* __restrict__ W2, const float* __restrict__ Wv,
           const float* __restrict__ Wf, const float* __restrict__ beta,
           const float* __restrict__ g1w, const float* __restrict__ g2w,
           __nv_bfloat16* __restrict__ Wc, __nv_bfloat16* __restrict__ wfm,
           __nv_bfloat16* __restrict__ W1t, __nv_bfloat16* __restrict__ Wvb,
           __nv_bfloat16* __restrict__ g2wb) {
    int i = blockIdx.x * 256 + threadIdx.x;
    if (i < N_WC) {
        int row = i / 352, j = i - row * 352;
        float4 f = make_float4(0.f, 0.f, 0.f, 0.f);
        float sc = 1.f;
        if (row < 1024) {
            if (j < 256)      f = ((const float4*)W2)[(size_t)row * 256 + j];
            else if (j < 320) { f = ((const float4*)Wf)[(size_t)row * 64 + (j - 256)]; sc = beta[0]; }
        } else {
            int p = row - 1024;
            if (j < 256)      f = ((const float4*)g1w)[(size_t)p * 288 + j];
            else if (j >= 320) f = ((const float4*)g1w)[(size_t)p * 288 + 256 + (j - 320)];
        }
        __nv_bfloat162* o = (__nv_bfloat162*)(Wc + (size_t)row * KQM + j * 4);
        o[0] = __floats2bfloat162_rn(f.x * sc, f.y * sc);
        o[1] = __floats2bfloat162_rn(f.z * sc, f.w * sc);
        return;
    }
    i -= N_WC;
    if (i < N_WFM) {
        int c = i / 352, j = i - c * 352;
        float4 f;
        if (j < 256)      f = ((const float4*)w)[(size_t)c * 256 + j];
        else if (j < 320) f = ((const float4*)fC)[(size_t)c * 64 + (j - 256)];
        else {
            float4 a = make_float4(0.f, 0.f, 0.f, 0.f);
            const float4* ep = (const float4*)Et + (size_t)c * 64 * 32 + (j - 320);
            #pragma unroll 8
            for (int kt = 0; kt < 64; kt++) {
                float4 e = ep[kt * 32];
                a.x += e.x; a.y += e.y; a.z += e.z; a.w += e.w;
            }
            f = make_float4(a.x * (1.f/64.f), a.y * (1.f/64.f), a.z * (1.f/64.f), a.w * (1.f/64.f));
        }
        __nv_bfloat162* o = (__nv_bfloat162*)(wfm + (size_t)c * KQM + j * 4);
        o[0] = __floats2bfloat162_rn(f.x, f.y);
        o[1] = __floats2bfloat162_rn(f.z, f.w);
        return;
    }
    i -= N_WFM;
    if (i < N_G2) {
        float4 f = ((const float4*)g2w)[i];
        __nv_bfloat162* o = (__nv_bfloat162*)(g2wb + (size_t)i * 4);
        o[0] = __floats2bfloat162_rn(f.x, f.y);
        o[1] = __floats2bfloat162_rn(f.z, f.w);
        return;
    }
    i -= N_G2;
    if (i < N_WV) {
        float4 f = ((const float4*)Wv)[i];
        __nv_bfloat162* o = (__nv_bfloat162*)(Wvb + (size_t)i * 4);
        o[0] = __floats2bfloat162_rn(f.x, f.y);
        o[1] = __floats2bfloat162_rn(f.z, f.w);
        return;
    }
    i -= N_WV;
    if (i < N_W1T) {
        int d = i & 127;
        int x = (i >> 7) % DX;
        int h = i / (DX * DHH);
        W1t[i] = __float2bfloat16(W1[(size_t)(h * DHH + d) * DX + x]);
    }
}

// ---------------- GEMM body (128x128 tile, A@B^T), BK=64, 256 threads ----------------
#define GEMM_SMEM (2 * 2 * 128 * 72 * 2)    // 73728 bytes
#define SAIDX(buf, row, col) (((buf) * 128 + (row)) * 72 + (col))

__device__ __forceinline__ void gemm_body(
    int mode, __nv_bfloat16* sm,
    const __nv_bfloat16* __restrict__ A, const __nv_bfloat16* __restrict__ B,
    void* __restrict__ Out,
    int lda, int ldb, int ldc, int K, int m0, int n0, int czoff,
    const float* __restrict__ e1, const float* __restrict__ e2)
{
    __nv_bfloat16* sA = sm;
    __nv_bfloat16* sB = sm + 2 * 128 * 72;
    const int tid  = threadIdx.x;
    const int lane = tid & 31, warp = tid >> 5;
    const int wm = (warp >> 1) << 5;
    const int wn = (warp & 1) << 6;

    float acc[2][8][4];
    #pragma unroll
    for (int i = 0; i < 2; i++)
        #pragma unroll
        for (int j = 0; j < 8; j++)
            #pragma unroll
            for (int r = 0; r < 4; r++) acc[i][j][r] = 0.f;

    auto tile_load = [&](int buf, int kt) {
        #pragma unroll
        for (int r = 0; r < 4; r++) {
            int id  = tid + (r << 8);
            int row = id >> 3;
            int cc  = (id & 7) << 3;
            cpasync16(&sA[SAIDX(buf, row, cc)], A + (size_t)(m0 + row) * lda + kt + cc);
            cpasync16(&sB[SAIDX(buf, row, cc)], B + (size_t)(n0 + row) * ldb + kt + cc);
        }
    };

    tile_load(0, 0);
    cp_commit();
    const int nk = K >> 6;
    for (int t = 0; t < nk; t++) {
        if (t + 1 < nk) {
            tile_load((t + 1) & 1, (t + 1) << 6);
            cp_commit();
            cp_wait<1>();
        } else {
            cp_wait<0>();
        }
        __syncthreads();
        const int buf = t & 1;
        #pragma unroll
        for (int s = 0; s < 4; s++) {
            const int colb = (s << 4) + ((lane >> 4) << 3);
            uint32_t af[2][4], bfr[4][4];
            #pragma unroll
            for (int i = 0; i < 2; i++)
                ldm_x4(af[i], &sA[SAIDX(buf, wm + (i << 4) + (lane & 15), colb)]);
            #pragma unroll
            for (int j = 0; j < 4; j++)
                ldm_x4(bfr[j], &sB[SAIDX(buf, wn + (j << 4) + (lane & 15), colb)]);
            #pragma unroll
            for (int i = 0; i < 2; i++)
                #pragma unroll
                for (int j = 0; j < 4; j++) {
                    mma16816(acc[i][2 * j],     af[i], bfr[j][0], bfr[j][2]);
                    mma16816(acc[i][2 * j + 1], af[i], bfr[j][1], bfr[j][3]);
                }
        }
        __syncthreads();
    }

    #pragma unroll
    for (int i = 0; i < 2; i++) {
        #pragma unroll
        for (int j = 0; j < 8; j++) {
            const int colg = n0 + wn + (j << 3) + ((lane & 3) << 1);
            #pragma unroll
            for (int r2 = 0; r2 < 2; r2++) {
                const int row = m0 + wm + (i << 4) + (lane >> 2) + (r2 << 3);
                float v0 = acc[i][j][r2 * 2], v1 = acc[i][j][r2 * 2 + 1];
                const size_t oidx = (size_t)row * ldc + czoff + colg;
                if (mode == 2) {
                    v0 = 1.f / (1.f + __expf(-(v0 + e1[colg])));
                    v1 = 1.f / (1.f + __expf(-(v1 + e1[colg + 1])));
                    *(float2*)((float*)Out + oidx) = make_float2(v0, v1);
                } else { // mode 1: plain bf16
                    *(__nv_bfloat162*)((__nv_bfloat16*)Out + oidx) =
                        __floats2bfloat162_rn(v0, v1);
                }
            }
        }
    }
}

// ---------------- GEMM body2 (256x128 tile, A@B^T), BK=64, 512 threads ----------------
// smem: sA [2][256][72], sB [2][128][72]  (72 = 64+8 pad, conflict-free ldmatrix)
#define GEMM2_SMEM ((2 * 256 + 2 * 128) * 72 * 2)   // 110592 bytes
#define S2A(buf, row, col) (((buf) * 256 + (row)) * 72 + (col))
#define S2B(buf, row, col) (((buf) * 128 + (row)) * 72 + (col))

__device__ __forceinline__ void gemm_body2(
    int mode, __nv_bfloat16* sm,
    const __nv_bfloat16* __restrict__ A, const __nv_bfloat16* __restrict__ B,
    void* __restrict__ Out,
    int lda, int ldb, int ldc, int K, int m0, int n0, int czoff,
    const float* __restrict__ e1, const float* __restrict__ e2)
{
    __nv_bfloat16* sA = sm;
    __nv_bfloat16* sB = sm + 2 * 256 * 72;
    const int tid  = threadIdx.x;
    const int lane = tid & 31, warp = tid >> 5;   // 16 warps
    const int wm = (warp >> 2) << 6;              // 0,64,128,192
    const int wn = (warp & 3) << 5;               // 0,32,64,96

    float acc[4][4][4];
    #pragma unroll
    for (int i = 0; i < 4; i++)
        #pragma unroll
        for (int j = 0; j < 4; j++)
            #pragma unroll
            for (int r = 0; r < 4; r++) acc[i][j][r] = 0.f;

    auto tile_load = [&](int buf, int kt) {
        #pragma unroll
        for (int r = 0; r < 4; r++) {                       // A: 2048 chunks
            int id  = tid + (r << 9);
            int row = id >> 3;
            int cc  = (id & 7) << 3;
            cpasync16(&sA[S2A(buf, row, cc)], A + (size_t)(m0 + row) * lda + kt + cc);
        }
        #pragma unroll
        for (int r = 0; r < 2; r++) {                       // B: 1024 chunks
            int id  = tid + (r << 9);
            int row = id >> 3;
            int cc  = (id & 7) << 3;
            cpasync16(&sB[S2B(buf, row, cc)], B + (size_t)(n0 + row) * ldb + kt + cc);
        }
    };

    tile_load(0, 0);
    cp_commit();
    const int nk = K >> 6;
    for (int t = 0; t < nk; t++) {
        if (t + 1 < nk) {
            tile_load((t + 1) & 1, (t + 1) << 6);
            cp_commit();
            cp_wait<1>();
        } else {
            cp_wait<0>();
        }
        __syncthreads();
        const int buf = t & 1;
        #pragma unroll
        for (int s = 0; s < 4; s++) {
            const int colb = (s << 4) + ((lane >> 4) << 3);
            uint32_t af[4][4], bfr[2][4];
            #pragma unroll
            for (int i = 0; i < 4; i++)
                ldm_x4(af[i], &sA[S2A(buf, wm + (i << 4) + (lane & 15), colb)]);
            #pragma unroll
            for (int jb = 0; jb < 2; jb++)
                ldm_x4(bfr[jb], &sB[S2B(buf, wn + (jb << 4) + (lane & 15), colb)]);
            #pragma unroll
            for (int i = 0; i < 4; i++)
                #pragma unroll
                for (int jb = 0; jb < 2; jb++) {
                    mma16816(acc[i][2 * jb],     af[i], bfr[jb][0], bfr[jb][2]);
                    mma16816(acc[i][2 * jb + 1], af[i], bfr[jb][1], bfr[jb][3]);
                }
        }
        __syncthreads();
    }

    #pragma unroll
    for (int i = 0; i < 4; i++) {
        #pragma unroll
        for (int j = 0; j < 4; j++) {
            const int colg = n0 + wn + (j << 3) + ((lane & 3) << 1);
            #pragma unroll
            for (int r2 = 0; r2 < 2; r2++) {
                const int row = m0 + wm + (i << 4) + (lane >> 2) + (r2 << 3);
                float v0 = acc[i][j][r2 * 2], v1 = acc[i][j][r2 * 2 + 1];
                const size_t oidx = (size_t)row * ldc + czoff + colg;
                if (mode == 0) {            // QH: cols>=1024 relu+g1b; all bf16
                    if (colg >= 1024) {
                        v0 = fmaxf(v0 + e1[colg - 1024], 0.f);
                        v1 = fmaxf(v1 + e1[colg - 1023], 0.f);
                    }
                    *(__nv_bfloat162*)((__nv_bfloat16*)Out + oidx) =
                        __floats2bfloat162_rn(v0, v1);
                } else {                    // mode 3: U = w + g*v (f32)
                    v0 = e2[oidx] + e1[oidx] * v0;
                    v1 = e2[oidx + 1] + e1[oidx + 1] * v1;
                    *(float2*)((float*)Out + oidx) = make_float2(v0, v1);
                }
            }
        }
    }
}

__global__ void __launch_bounds__(512)
gemm_qh_k(const __nv_bfloat16* __restrict__ wfm, const __nv_bfloat16* __restrict__ Wc,
          __nv_bfloat16* __restrict__ QH, const float* __restrict__ g1b) {
    extern __shared__ __nv_bfloat16 smg[];
    gdc_wait();   // wfm/Wc come from prep
    gemm_body2(0, smg, wfm, Wc, QH, KQM, KQM, 2048, KQM,
               blockIdx.y << 8, blockIdx.x << 7, 0, g1b, nullptr);
}

// ---------------- fat kernel: qt path (A-reuse, 9 B-tiles) + gate-sigmoid path ----------------
#define FAT_SMEM (3 * 128 * 136 * 2)    // 104448
#define QIDX(row, col) ((row) * 136 + (col))

__global__ void __launch_bounds__(256)
gemm_fat_k(const __nv_bfloat16* __restrict__ QH, const __nv_bfloat16* __restrict__ W1t,
           __nv_bfloat16* __restrict__ qt, const __nv_bfloat16* __restrict__ g2wb,
           float* __restrict__ gbuf, const float* __restrict__ g2b) {
    extern __shared__ __nv_bfloat16 smg[];
    gdc_wait();   // QH comes from gemm_qh
    const int bid = blockIdx.x;
    if (bid < 128) {
        const int h = bid >> 4, by = bid & 15;
        const int m0 = by << 7;
        const int tid = threadIdx.x;
        const int lane = tid & 31, warp = tid >> 5;
        const int wm = (warp >> 1) << 5;
        const int wn = (warp & 1) << 6;
        __nv_bfloat16* sA = smg;
        __nv_bfloat16* sB = smg + 128 * 136;
        const __nv_bfloat16* Bp = W1t + (size_t)h * DX * DHH;

        #pragma unroll
        for (int r = 0; r < 8; r++) {
            int id = tid + (r << 8);
            int row = id >> 4, cc = (id & 15) << 3;
            cpasync16(&sA[QIDX(row, cc)], QH + (size_t)(m0 + row) * 2048 + h * 128 + cc);
        }
        auto bload = [&](int buf, int n0) {
            #pragma unroll
            for (int r = 0; r < 8; r++) {
                int id = tid + (r << 8);
                int row = id >> 4, cc = (id & 15) << 3;
                cpasync16(&sB[(buf * 128 + row) * 136 + cc], Bp + (size_t)(n0 + row) * DHH + cc);
            }
        };
        bload(0, 0);
        cp_commit();

        for (int bx = 0; bx < 9; bx++) {
            if (bx + 1 < 9) {
                bload((bx + 1) & 1, (bx + 1) << 7);
                cp_commit();
                cp_wait<1>();
            } else {
                cp_wait<0>();
            }
            __syncthreads();
            float acc[2][8][4];
            #pragma unroll
            for (int i = 0; i < 2; i++)
                #pragma unroll
                for (int j = 0; j < 8; j++)
                    #pragma unroll
                    for (int r = 0; r < 4; r++) acc[i][j][r] = 0.f;
            const int bufo = (bx & 1) * 128;
            #pragma unroll
            for (int s = 0; s < 8; s++) {
                const int colb = (s << 4) + ((lane >> 4) << 3);
                uint32_t af[2][4], bfr[4][4];
                #pragma unroll
                for (int i = 0; i < 2; i++)
                    ldm_x4(af[i], &sA[QIDX(wm + (i << 4) + (lane & 15), colb)]);
                #pragma unroll
                for (int j = 0; j < 4; j++)
                    ldm_x4(bfr[j], &sB[(bufo + wn + (j << 4) + (lane & 15)) * 136 + colb]);
                #pragma unroll
                for (int i = 0; i < 2; i++)
                    #pragma unroll
                    for (int j = 0; j < 4; j++) {
                        mma16816(acc[i][2 * j],     af[i], bfr[j][0], bfr[j][2]);
                        mma16816(acc[i][2 * j + 1], af[i], bfr[j][1], bfr[j][3]);
                    }
            }
            const int n0 = bx << 7;
            #pragma unroll
            for (int i = 0; i < 2; i++) {
                #pragma unroll
                for (int j = 0; j < 8; j++) {
                    const int colg = n0 + wn + (j << 3) + ((lane & 3) << 1);
                    #pragma unroll
                    for (int r2 = 0; r2 < 2; r2++) {
                        const int row = m0 + wm + (i << 4) + (lane >> 2) + (r2 << 3);
                        *(__nv_bfloat162*)(qt + (size_t)row * (NH * DX) + h * DX + colg) =
                            __floats2bfloat162_rn(acc[i][j][r2 * 2], acc[i][j][r2 * 2 + 1]);
                    }
                }
            }
            __syncthreads();
        }
    } else {
        int b2 = bid - 128;
        int by = b2 >> 3, bx = b2 & 7;
        gemm_body(2, smg, QH + 1024, g2wb, gbuf,
                  2048, PHH, DD, PHH, by << 7, bx << 7, 0, g2b, nullptr);
    }
}

__global__ void __launch_bounds__(512)
gemm_gate_k(const __nv_bfloat16* __restrict__ Z, const __nv_bfloat16* __restrict__ Wvb,
            float* __restrict__ U, const float* __restrict__ gbuf,
            const float* __restrict__ w) {
    extern __shared__ __nv_bfloat16 smg[];
    gdc_wait();   // Z comes from attn
    gemm_body2(3, smg, Z + blockIdx.z * DX, Wvb + (size_t)blockIdx.z * DHH * DX, U,
               NH * DX, DX, DD, DX, blockIdx.y << 8, 0, blockIdx.z * DHH,
               gbuf, w);
}

// ---------------- fused attention core: 1024 threads, 2 c's/CTA, full prefetch chain ----------
#define FPW 580
#define SM_FP 0
#define SM_QT (64 * FPW)               // 37120
#define SM_SC (SM_QT + 8 * FPW)        // 41760 (8 parts x 512 f32 = 4096)
#define SM_AT (SM_SC + 4096)           // 45856
#define ATTN_SMEM ((SM_AT + 576) * 4)  // 185728 bytes

__global__ void __launch_bounds__(1024, 1)
attn_fused_k(const float* __restrict__ F, const float* __restrict__ Et,
             const __nv_bfloat16* __restrict__ qtg, __nv_bfloat16* __restrict__ Z) {
    extern __shared__ uint32_t smem_u[];
    uint32_t* fp_s = smem_u + SM_FP;
    uint32_t* qt_s = smem_u + SM_QT;
    float*    sc_s = (float*)(smem_u + SM_SC);
    __nv_bfloat16* at_s = (__nv_bfloat16*)(smem_u + SM_AT);

    const int tid = threadIdx.x;
    const int wid = tid >> 5, lane = tid & 31;

    if (tid < 288) ((uint32_t*)(at_s + 8 * 72))[tid] = 0;   // pad rows 8-15 (persist both iters)

    #pragma unroll 1
    for (int it = 0; it < 2; it++) {
        const int c = blockIdx.x + (it << 10);
        if (it) __syncthreads();

        // F/Et are external inputs: load BEFORE the PDL wait
        {
            #pragma unroll
            for (int rr = 0; rr < 2; rr++) {
                const int row = (wid << 1) + rr;
                const float4* fF = (const float4*)F  + ((size_t)c * 64 + row) * 256;
                const float4* fE = (const float4*)Et + ((size_t)c * 64 + row) * 32;
                uint32_t* dst = fp_s + row * FPW;
                #pragma unroll
                for (int k2 = 0; k2 < 9; k2++) {
                    const int j = lane + (k2 << 5);
                    float4 v = (j < 256) ? fF[j] : fE[j - 256];
                    uint2 pk;
                    pk.x = packbf2(v.x, v.y);
                    pk.y = packbf2(v.z, v.w);
                    *(uint2*)(dst + j * 2) = pk;
                }
            }
        }
        if (it == 0) gdc_wait();   // qt produced by gemm_fat
        for (int i = tid; i < 8 * 288; i += 1024) {
            int row = i / 288, j = i - row * 288;
            uint2 v = ((const uint2*)(qtg + (size_t)c * (NH * DX) + row * DX))[j];
            *(uint2*)(qt_s + row * FPW + j * 2) = v;
        }
        __syncthreads();

        // prefetch chain
        {
            int c2 = -1;
            if (it == 0)                        c2 = blockIdx.x + 1024;
            else if (blockIdx.x + 148 < 1024)   c2 = blockIdx.x + 148;
            if (c2 >= 0) {
                const char* pf = (const char*)(F + (size_t)c2 * 64 * 1024);
                #pragma unroll
                for (int r = 0; r < 2; r++) prefetchL2(pf + (tid + (r << 10)) * 128);
                const char* pe = (const char*)(Et + (size_t)c2 * 64 * 128);
                if (tid < 256) prefetchL2(pe + tid * 128);
                const char* pq = (const char*)(qtg + (size_t)c2 * (NH * DX));
                if (tid >= 256 && tid < 400) prefetchL2(pq + (tid - 256) * 128);
            }
        }

        // phase 1: scores[64,8] = Fp @ qt^T
        {
            const int t = wid & 3;
            const int p = wid >> 2;
            const char* aP = (const char*)fp_s + (t * 16 + (lane & 15)) * 2320
                             + (lane >> 4) * 16 + p * 288;
            const char* bP = (const char*)qt_s + (lane & 7) * 2320
                             + (lane >> 4) * 16 + p * 288;
            float cacc[4] = {0.f, 0.f, 0.f, 0.f};
            #pragma unroll 3
            for (int kk = 0; kk < 9; kk++) {
                uint32_t a[4], b[4];
                ldm_x4(a, aP + kk * 32);
                ldm_x4(b, bP + kk * 32);
                mma16816(cacc, a, b[0], b[2]);
            }
            const int kr = t * 16 + (lane >> 2);
            const int h0 = (lane & 3) << 1;
            float* ps = sc_s + p * 512;
            ps[h0 * 64 + kr]           = cacc[0];
            ps[(h0 + 1) * 64 + kr]     = cacc[1];
            ps[h0 * 64 + kr + 8]       = cacc[2];
            ps[(h0 + 1) * 64 + kr + 8] = cacc[3];
        }
        __syncthreads();

        // phase 2: reduce + softmax per head (warps 0-7)
        if (wid < 8) {
            const float sc = 0.08838834764831845f;
            float v0 = 0.f, v1 = 0.f;
            #pragma unroll
            for (int p = 0; p < 8; p++) {
                v0 += sc_s[p * 512 + wid * 64 + lane];
                v1 += sc_s[p * 512 + wid * 64 + lane + 32];
            }
            v0 *= sc; v1 *= sc;
            float m = fmaxf(v0, v1);
            #pragma unroll
            for (int o = 16; o; o >>= 1) m = fmaxf(m, __shfl_xor_sync(0xffffffffu, m, o));
            float e0 = __expf(v0 - m), e1 = __expf(v1 - m);
            float s = e0 + e1;
            #pragma unroll
            for (int o = 16; o; o >>= 1) s += __shfl_xor_sync(0xffffffffu, s, o);
            float inv = 1.f / s;
            at_s[wid * 72 + lane]      = __float2bfloat16(e0 * inv);
            at_s[wid * 72 + lane + 32] = __float2bfloat16(e1 * inv);
        }
        __syncthreads();

        // phase 3: z[8,1152] = attn @ Fp
        {
            uint32_t afr[4][4];
            const char* aP = (const char*)at_s + (lane & 15) * 144 + (lane >> 4) * 16;
            #pragma unroll
            for (int kk = 0; kk < 4; kk++) ldm_x4(afr[kk], aP + kk * 32);

            const int brow = (lane & 7) + ((lane >> 3) & 1) * 8;
            const int bcol = (lane >> 4) * 8;
            for (int xt = wid; xt < 72; xt += 32) {
                const int x0 = xt * 16;
                const char* bP = (const char*)fp_s + brow * 2320 + (x0 + bcol) * 2;
                float c0[4] = {0.f, 0.f, 0.f, 0.f}, c1[4] = {0.f, 0.f, 0.f, 0.f};
                #pragma unroll
                for (int kk = 0; kk < 4; kk++) {
                    uint32_t b[4];
                    ldm_x4t(b, bP + kk * 16 * 2320);
                    mma16816(c0, afr[kk], b[0], b[1]);
                    mma16816(c1, afr[kk], b[2], b[3]);
                }
                const int h = lane >> 2, xo = (lane & 3);
                uint32_t* zo = (uint32_t*)(Z + (size_t)c * (NH * DX) + h * DX + x0);
                zo[xo]     = packbf2(c0[0], c0[1]);
                zo[xo + 4] = packbf2(c1[0], c1[1]);
            }
        }
    }
}

// ---------------- finalize: out = U / max(||U||, eps) ----------------
__global__ void __launch_bounds__(256)
finalize_k(const float* __restrict__ U, float* __restrict__ out) {
    gdc_wait();
    const int c = blockIdx.x, tid = threadIdx.x;
    const int wid = tid >> 5, lane = tid & 31;
    __shared__ float sred[8];
    float u[4]; float ss = 0.f;
    #pragma unroll
    for (int i = 0; i < 4; i++) {
        u[i] = U[(size_t)c * DD + i * 256 + tid];
        ss += u[i] * u[i];
    }
    #pragma unroll
    for (int o = 16; o; o >>= 1) ss += __shfl_xor_sync(0xffffffffu, ss, o);
    if (lane == 0) sred[wid] = ss;
    __syncthreads();
    float tot = 0.f;
    #pragma unroll
    for (int h = 0; h < 8; h++) tot += sred[h];
    float inv = 1.f / fmaxf(sqrtf(tot), 1e-12f);
    #pragma unroll
    for (int i = 0; i < 4; i++)
        out[(size_t)c * DD + i * 256 + tid] = u[i] * inv;
}

// ---------------- launch ----------------
template <typename K, typename... Args>
static void launch_pdl(K kern, dim3 grid, dim3 block, size_t smem, Args... args) {
    cudaLaunchConfig_t cfg = {};
    cfg.gridDim = grid;
    cfg.blockDim = block;
    cfg.dynamicSmemBytes = smem;
    cudaLaunchAttribute attr[1];
    attr[0].id = cudaLaunchAttributeProgrammaticStreamSerialization;
    attr[0].val.programmaticStreamSerializationAllowed = 1;
    cfg.attrs = attr;
    cfg.numAttrs = 1;
    cudaLaunchKernelEx(&cfg, kern, args...);
}

extern "C" void kernel_launch(void* const* d_in, const int* in_sizes, int n_in,
                              void* d_out, int out_size) {
    const float* w   = (const float*)d_in[0];
    const float* F   = (const float*)d_in[1];
    const float* Et  = (const float*)d_in[2];
    const float* fC  = (const float*)d_in[3];
    const float* W1  = (const float*)d_in[4];
    const float* W2  = (const float*)d_in[5];
    const float* Wv  = (const float*)d_in[6];
    const float* Wf  = (const float*)d_in[7];
    // alpha (d_in[8]) cancels in softmax — unused
    const float* beta = (const float*)d_in[9];
    const float* g1w = (const float*)d_in[10];
    const float* g1b = (const float*)d_in[11];
    const float* g2w = (const float*)d_in[12];
    const float* g2b = (const float*)d_in[13];
    float* out = (float*)d_out;

    __nv_bfloat16 *Wc, *wfm, *QH, *W1t, *Wvb, *g2wb, *qt, *Z;
    float *gbuf, *U;
    cudaGetSymbolAddress((void**)&Wc,   g_Wc);
    cudaGetSymbolAddress((void**)&wfm,  g_wfm);
    cudaGetSymbolAddress((void**)&QH,   g_QH);
    cudaGetSymbolAddress((void**)&W1t,  g_W1t);
    cudaGetSymbolAddress((void**)&Wvb,  g_Wvb);
    cudaGetSymbolAddress((void**)&g2wb, g_g2wb);
    cudaGetSymbolAddress((void**)&qt,   g_qt);
    cudaGetSymbolAddress((void**)&Z,    g_Z);
    cudaGetSymbolAddress((void**)&gbuf, g_g);
    cudaGetSymbolAddress((void**)&U,    g_U);

    cudaFuncSetAttribute(attn_fused_k, cudaFuncAttributeMaxDynamicSharedMemorySize, ATTN_SMEM);
    cudaFuncSetAttribute(gemm_qh_k,   cudaFuncAttributeMaxDynamicSharedMemorySize, GEMM2_SMEM);
    cudaFuncSetAttribute(gemm_fat_k,  cudaFuncAttributeMaxDynamicSharedMemorySize, FAT_SMEM);
    cudaFuncSetAttribute(gemm_gate_k, cudaFuncAttributeMaxDynamicSharedMemorySize, GEMM2_SMEM);

    prep_fat_k<<<PREP_TOTAL / 256, 256>>>(w, Et, fC, W1, W2, Wv, Wf, beta, g1w, g2w,
                                          Wc, wfm, W1t, Wvb, g2wb);
    launch_pdl(gemm_qh_k, dim3(16, 8), dim3(512), GEMM2_SMEM, wfm, Wc, QH, g1b);
    launch_pdl(gemm_fat_k, dim3(256), dim3(256), FAT_SMEM, QH, W1t, qt, g2wb, gbuf, g2b);
    launch_pdl(attn_fused_k, dim3(1024), dim3(1024), (size_t)ATTN_SMEM, F, Et, qt, Z);
    launch_pdl(gemm_gate_k, dim3(1, 8, 8), dim3(512), GEMM2_SMEM, Z, Wvb, U, gbuf, w);
    launch_pdl(finalize_k, dim3(CC), dim3(256), (size_t)0, U, out);
}

// round 17
// speedup vs baseline: 1.0849x; 1.0849x over previous
#include <cuda_runtime.h>
#include <cuda_bf16.h>
#include <cstdint>

// ---------------- problem dims ----------------
#define CC   2048
#define KTT  64
#define DD   1024
#define DE   128
#define DF   256
#define NH   8
#define DHH  128
#define DX   1152   // D + De
#define PHH  1024
#define KQM  1408   // D + Df + De  (merged Q/gate1 GEMM K)

// ---------------- scratch (__device__ globals; no allocations) ----------------
__device__ __align__(128) __nv_bfloat16 g_Wc[2048 * KQM];        // [W2|b*Wf|0 ; g1w_D|0|g1w_De]
__device__ __align__(128) __nv_bfloat16 g_wfm[CC * KQM];         // [w | fC | mean(Et)]
__device__ __align__(128) __nv_bfloat16 g_QH[CC * 2048];         // [Q | hmid]
__device__ __align__(128) __nv_bfloat16 g_W1t[NH * DX * DHH];    // [h][x][d]
__device__ __align__(128) __nv_bfloat16 g_Wvb[DD * DX];
__device__ __align__(128) __nv_bfloat16 g_g2wb[DD * PHH];
__device__ __align__(128) __nv_bfloat16 g_qt[(size_t)CC * NH * DX];
__device__ __align__(128) __nv_bfloat16 g_Z[(size_t)CC * NH * DX];
__device__ __align__(128) float g_g[CC * DD];
__device__ __align__(128) float g_U[CC * DD];

// ---------------- PTX helpers ----------------
__device__ __forceinline__ void cpasync16(void* dst, const void* src) {
    uint32_t d = (uint32_t)__cvta_generic_to_shared(dst);
    asm volatile("cp.async.cg.shared.global [%0], [%1], 16;\n" :: "r"(d), "l"(src));
}
__device__ __forceinline__ void cp_commit() {
    asm volatile("cp.async.commit_group;\n" ::: "memory");
}
template <int N>
__device__ __forceinline__ void cp_wait() {
    asm volatile("cp.async.wait_group %0;\n" :: "n"(N) : "memory");
}
__device__ __forceinline__ void ldm_x4(uint32_t* r, const void* p) {
    uint32_t a = (uint32_t)__cvta_generic_to_shared(p);
    asm volatile("ldmatrix.sync.aligned.m8n8.x4.shared.b16 {%0,%1,%2,%3}, [%4];\n"
                 : "=r"(r[0]), "=r"(r[1]), "=r"(r[2]), "=r"(r[3]) : "r"(a));
}
__device__ __forceinline__ void ldm_x4t(uint32_t* r, const void* p) {
    uint32_t a = (uint32_t)__cvta_generic_to_shared(p);
    asm volatile("ldmatrix.sync.aligned.m8n8.x4.trans.shared.b16 {%0,%1,%2,%3}, [%4];\n"
                 : "=r"(r[0]), "=r"(r[1]), "=r"(r[2]), "=r"(r[3]) : "r"(a));
}
__device__ __forceinline__ void mma16816(float* c, const uint32_t* a, uint32_t b0, uint32_t b1) {
    asm volatile(
        "mma.sync.aligned.m16n8k16.row.col.f32.bf16.bf16.f32 "
        "{%0,%1,%2,%3},{%4,%5,%6,%7},{%8,%9},{%0,%1,%2,%3};\n"
        : "+f"(c[0]), "+f"(c[1]), "+f"(c[2]), "+f"(c[3])
        : "r"(a[0]), "r"(a[1]), "r"(a[2]), "r"(a[3]), "r"(b0), "r"(b1));
}
__device__ __forceinline__ uint32_t packbf2(float a, float b) {
    __nv_bfloat162 t = __floats2bfloat162_rn(a, b);
    return *(uint32_t*)&t;
}
__device__ __forceinline__ void prefetchL2(const void* p) {
    asm volatile("prefetch.global.L2 [%0];" :: "l"(p));
}
__device__ __forceinline__ void gdc_wait() {
    asm volatile("griddepcontrol.wait;" ::: "memory");
}

// ---------------- fat prep kernel ----------------
#define N_WC  (2048 * 352)
#define N_WFM (2048 * 352)
#define N_G2  (1024 * 1024 / 4)
#define N_WV  (1024 * 1152 / 4)
#define N_W1T (8 * 1152 * 128)
#define PREP_TOTAL (N_WC + N_WFM + N_G2 + N_WV + N_W1T)

__global__ void __launch_bounds__(256)
prep_fat_k(const float* __restrict__ w, const float* __restrict__ Et,
           const float* __restrict__ fC, const float* __restrict__ W1,
           const float* __restrict__ W2, const float* __restrict__ Wv,
           const float* __restrict__ Wf, const float* __restrict__ beta,
           const float* __restrict__ g1w, const float* __restrict__ g2w,
           __nv_bfloat16* __restrict__ Wc, __nv_bfloat16* __restrict__ wfm,
           __nv_bfloat16* __restrict__ W1t, __nv_bfloat16* __restrict__ Wvb,
           __nv_bfloat16* __restrict__ g2wb) {
    int i = blockIdx.x * 256 + threadIdx.x;
    if (i < N_WC) {
        int row = i / 352, j = i - row * 352;
        float4 f = make_float4(0.f, 0.f, 0.f, 0.f);
        float sc = 1.f;
        if (row < 1024) {
            if (j < 256)      f = ((const float4*)W2)[(size_t)row * 256 + j];
            else if (j < 320) { f = ((const float4*)Wf)[(size_t)row * 64 + (j - 256)]; sc = beta[0]; }
        } else {
            int p = row - 1024;
            if (j < 256)      f = ((const float4*)g1w)[(size_t)p * 288 + j];
            else if (j >= 320) f = ((const float4*)g1w)[(size_t)p * 288 + 256 + (j - 320)];
        }
        __nv_bfloat162* o = (__nv_bfloat162*)(Wc + (size_t)row * KQM + j * 4);
        o[0] = __floats2bfloat162_rn(f.x * sc, f.y * sc);
        o[1] = __floats2bfloat162_rn(f.z * sc, f.w * sc);
        return;
    }
    i -= N_WC;
    if (i < N_WFM) {
        int c = i / 352, j = i - c * 352;
        float4 f;
        if (j < 256)      f = ((const float4*)w)[(size_t)c * 256 + j];
        else if (j < 320) f = ((const float4*)fC)[(size_t)c * 64 + (j - 256)];
        else {
            float4 a = make_float4(0.f, 0.f, 0.f, 0.f);
            const float4* ep = (const float4*)Et + (size_t)c * 64 * 32 + (j - 320);
            #pragma unroll 8
            for (int kt = 0; kt < 64; kt++) {
                float4 e = ep[kt * 32];
                a.x += e.x; a.y += e.y; a.z += e.z; a.w += e.w;
            }
            f = make_float4(a.x * (1.f/64.f), a.y * (1.f/64.f), a.z * (1.f/64.f), a.w * (1.f/64.f));
        }
        __nv_bfloat162* o = (__nv_bfloat162*)(wfm + (size_t)c * KQM + j * 4);
        o[0] = __floats2bfloat162_rn(f.x, f.y);
        o[1] = __floats2bfloat162_rn(f.z, f.w);
        return;
    }
    i -= N_WFM;
    if (i < N_G2) {
        float4 f = ((const float4*)g2w)[i];
        __nv_bfloat162* o = (__nv_bfloat162*)(g2wb + (size_t)i * 4);
        o[0] = __floats2bfloat162_rn(f.x, f.y);
        o[1] = __floats2bfloat162_rn(f.z, f.w);
        return;
    }
    i -= N_G2;
    if (i < N_WV) {
        float4 f = ((const float4*)Wv)[i];
        __nv_bfloat162* o = (__nv_bfloat162*)(Wvb + (size_t)i * 4);
        o[0] = __floats2bfloat162_rn(f.x, f.y);
        o[1] = __floats2bfloat162_rn(f.z, f.w);
        return;
    }
    i -= N_WV;
    if (i < N_W1T) {
        int d = i & 127;
        int x = (i >> 7) % DX;
        int h = i / (DX * DHH);
        W1t[i] = __float2bfloat16(W1[(size_t)(h * DHH + d) * DX + x]);
    }
}

// ---------------- GEMM body (128x128 tile, A@B^T), BK=64, dynamic smem ----------------
// smem: sA/sB each [2][128][72] bf16 (72 = 64 + 8 pad; word stride 36 -> conflict-free ldmatrix)
#define GEMM_SMEM (2 * 2 * 128 * 72 * 2)    // 73728 bytes
#define SAIDX(buf, row, col) (((buf) * 128 + (row)) * 72 + (col))

__device__ __forceinline__ void gemm_body(
    int mode, __nv_bfloat16* sm,
    const __nv_bfloat16* __restrict__ A, const __nv_bfloat16* __restrict__ B,
    void* __restrict__ Out,
    int lda, int ldb, int ldc, int K, int m0, int n0, int czoff,
    const float* __restrict__ e1, const float* __restrict__ e2)
{
    __nv_bfloat16* sA = sm;
    __nv_bfloat16* sB = sm + 2 * 128 * 72;
    const int tid  = threadIdx.x;
    const int lane = tid & 31, warp = tid >> 5;
    const int wm = (warp >> 1) << 5;
    const int wn = (warp & 1) << 6;

    float acc[2][8][4];
    #pragma unroll
    for (int i = 0; i < 2; i++)
        #pragma unroll
        for (int j = 0; j < 8; j++)
            #pragma unroll
            for (int r = 0; r < 4; r++) acc[i][j][r] = 0.f;

    auto tile_load = [&](int buf, int kt) {
        #pragma unroll
        for (int r = 0; r < 4; r++) {
            int id  = tid + (r << 8);
            int row = id >> 3;
            int cc  = (id & 7) << 3;
            cpasync16(&sA[SAIDX(buf, row, cc)], A + (size_t)(m0 + row) * lda + kt + cc);
            cpasync16(&sB[SAIDX(buf, row, cc)], B + (size_t)(n0 + row) * ldb + kt + cc);
        }
    };

    tile_load(0, 0);
    cp_commit();
    const int nk = K >> 6;
    for (int t = 0; t < nk; t++) {
        if (t + 1 < nk) {
            tile_load((t + 1) & 1, (t + 1) << 6);
            cp_commit();
            cp_wait<1>();
        } else {
            cp_wait<0>();
        }
        __syncthreads();
        const int buf = t & 1;
        #pragma unroll
        for (int s = 0; s < 4; s++) {
            const int colb = (s << 4) + ((lane >> 4) << 3);
            uint32_t af[2][4], bfr[4][4];
            #pragma unroll
            for (int i = 0; i < 2; i++)
                ldm_x4(af[i], &sA[SAIDX(buf, wm + (i << 4) + (lane & 15), colb)]);
            #pragma unroll
            for (int j = 0; j < 4; j++)
                ldm_x4(bfr[j], &sB[SAIDX(buf, wn + (j << 4) + (lane & 15), colb)]);
            #pragma unroll
            for (int i = 0; i < 2; i++)
                #pragma unroll
                for (int j = 0; j < 4; j++) {
                    mma16816(acc[i][2 * j],     af[i], bfr[j][0], bfr[j][2]);
                    mma16816(acc[i][2 * j + 1], af[i], bfr[j][1], bfr[j][3]);
                }
        }
        __syncthreads();
    }

    #pragma unroll
    for (int i = 0; i < 2; i++) {
        #pragma unroll
        for (int j = 0; j < 8; j++) {
            const int colg = n0 + wn + (j << 3) + ((lane & 3) << 1);
            #pragma unroll
            for (int r2 = 0; r2 < 2; r2++) {
                const int row = m0 + wm + (i << 4) + (lane >> 2) + (r2 << 3);
                float v0 = acc[i][j][r2 * 2], v1 = acc[i][j][r2 * 2 + 1];
                const size_t oidx = (size_t)row * ldc + czoff + colg;
                if (mode == 0) {
                    if (colg >= 1024) {
                        v0 = fmaxf(v0 + e1[colg - 1024], 0.f);
                        v1 = fmaxf(v1 + e1[colg - 1023], 0.f);
                    }
                    *(__nv_bfloat162*)((__nv_bfloat16*)Out + oidx) =
                        __floats2bfloat162_rn(v0, v1);
                } else if (mode == 1) {
                    *(__nv_bfloat162*)((__nv_bfloat16*)Out + oidx) =
                        __floats2bfloat162_rn(v0, v1);
                } else if (mode == 2) {
                    v0 = 1.f / (1.f + __expf(-(v0 + e1[colg])));
                    v1 = 1.f / (1.f + __expf(-(v1 + e1[colg + 1])));
                    *(float2*)((float*)Out + oidx) = make_float2(v0, v1);
                } else { // gate: U = w + g*v
                    v0 = e2[oidx] + e1[oidx] * v0;
                    v1 = e2[oidx + 1] + e1[oidx + 1] * v1;
                    *(float2*)((float*)Out + oidx) = make_float2(v0, v1);
                }
            }
        }
    }
}

__global__ void __launch_bounds__(256, 2)
gemm_qh_k(const __nv_bfloat16* __restrict__ wfm, const __nv_bfloat16* __restrict__ Wc,
          __nv_bfloat16* __restrict__ QH, const float* __restrict__ g1b) {
    extern __shared__ __nv_bfloat16 smg[];
    gdc_wait();   // wfm/Wc come from prep
    gemm_body(0, smg, wfm, Wc, QH, KQM, KQM, 2048, KQM,
              blockIdx.y << 7, blockIdx.x << 7, 0, g1b, nullptr);
}

// ---------------- fat kernel: qt path (A-reuse, 9 B-tiles) + gate-sigmoid path ----------------
// qt smem: sA [128][136] bf16 (34816 B) + sB [2][128][136] (69632 B) = 104448 B
// 128x128 tile load = 2048 x 16B chunks: row = id>>4 (16 chunks/row), cc = (id&15)<<3.
#define FAT_SMEM (3 * 128 * 136 * 2)    // 104448
#define QIDX(row, col) ((row) * 136 + (col))

__global__ void __launch_bounds__(256)
gemm_fat_k(const __nv_bfloat16* __restrict__ QH, const __nv_bfloat16* __restrict__ W1t,
           __nv_bfloat16* __restrict__ qt, const __nv_bfloat16* __restrict__ g2wb,
           float* __restrict__ gbuf, const float* __restrict__ g2b) {
    extern __shared__ __nv_bfloat16 smg[];
    gdc_wait();   // QH comes from gemm_qh
    const int bid = blockIdx.x;
    if (bid < 128) {
        // qt[:, h, :] = Q_h[128x128] @ W1_h^T, streaming 9 n-tiles with A resident
        const int h = bid >> 4, by = bid & 15;
        const int m0 = by << 7;
        const int tid = threadIdx.x;
        const int lane = tid & 31, warp = tid >> 5;
        const int wm = (warp >> 1) << 5;
        const int wn = (warp & 1) << 6;
        __nv_bfloat16* sA = smg;
        __nv_bfloat16* sB = smg + 128 * 136;
        const __nv_bfloat16* Bp = W1t + (size_t)h * DX * DHH;

        #pragma unroll
        for (int r = 0; r < 8; r++) {
            int id = tid + (r << 8);
            int row = id >> 4, cc = (id & 15) << 3;
            cpasync16(&sA[QIDX(row, cc)], QH + (size_t)(m0 + row) * 2048 + h * 128 + cc);
        }
        auto bload = [&](int buf, int n0) {
            #pragma unroll
            for (int r = 0; r < 8; r++) {
                int id = tid + (r << 8);
                int row = id >> 4, cc = (id & 15) << 3;
                cpasync16(&sB[(buf * 128 + row) * 136 + cc], Bp + (size_t)(n0 + row) * DHH + cc);
            }
        };
        bload(0, 0);
        cp_commit();

        for (int bx = 0; bx < 9; bx++) {
            if (bx + 1 < 9) {
                bload((bx + 1) & 1, (bx + 1) << 7);
                cp_commit();
                cp_wait<1>();
            } else {
                cp_wait<0>();
            }
            __syncthreads();
            float acc[2][8][4];
            #pragma unroll
            for (int i = 0; i < 2; i++)
                #pragma unroll
                for (int j = 0; j < 8; j++)
                    #pragma unroll
                    for (int r = 0; r < 4; r++) acc[i][j][r] = 0.f;
            const int bufo = (bx & 1) * 128;
            #pragma unroll
            for (int s = 0; s < 8; s++) {
                const int colb = (s << 4) + ((lane >> 4) << 3);
                uint32_t af[2][4], bfr[4][4];
                #pragma unroll
                for (int i = 0; i < 2; i++)
                    ldm_x4(af[i], &sA[QIDX(wm + (i << 4) + (lane & 15), colb)]);
                #pragma unroll
                for (int j = 0; j < 4; j++)
                    ldm_x4(bfr[j], &sB[(bufo + wn + (j << 4) + (lane & 15)) * 136 + colb]);
                #pragma unroll
                for (int i = 0; i < 2; i++)
                    #pragma unroll
                    for (int j = 0; j < 4; j++) {
                        mma16816(acc[i][2 * j],     af[i], bfr[j][0], bfr[j][2]);
                        mma16816(acc[i][2 * j + 1], af[i], bfr[j][1], bfr[j][3]);
                    }
            }
            const int n0 = bx << 7;
            #pragma unroll
            for (int i = 0; i < 2; i++) {
                #pragma unroll
                for (int j = 0; j < 8; j++) {
                    const int colg = n0 + wn + (j << 3) + ((lane & 3) << 1);
                    #pragma unroll
                    for (int r2 = 0; r2 < 2; r2++) {
                        const int row = m0 + wm + (i << 4) + (lane >> 2) + (r2 << 3);
                        *(__nv_bfloat162*)(qt + (size_t)row * (NH * DX) + h * DX + colg) =
                            __floats2bfloat162_rn(acc[i][j][r2 * 2], acc[i][j][r2 * 2 + 1]);
                    }
                }
            }
            __syncthreads();
        }
    } else {
        int b2 = bid - 128;
        int by = b2 >> 3, bx = b2 & 7;
        gemm_body(2, smg, QH + 1024, g2wb, gbuf,
                  2048, PHH, DD, PHH, by << 7, bx << 7, 0, g2b, nullptr);
    }
}

__global__ void __launch_bounds__(256, 2)
gemm_gate_k(const __nv_bfloat16* __restrict__ Z, const __nv_bfloat16* __restrict__ Wvb,
            float* __restrict__ U, const float* __restrict__ gbuf,
            const float* __restrict__ w) {
    extern __shared__ __nv_bfloat16 smg[];
    gdc_wait();   // Z comes from attn
    gemm_body(3, smg, Z + blockIdx.z * DX, Wvb + (size_t)blockIdx.z * DHH * DX, U,
              NH * DX, DX, DD, DX, blockIdx.y << 7, 0, blockIdx.z * DHH,
              gbuf, w);
}

// ---------------- fused attention core: 1024 threads, 2 c's/CTA, full prefetch chain ----------
#define FPW 580
#define SM_FP 0
#define SM_QT (64 * FPW)               // 37120
#define SM_SC (SM_QT + 8 * FPW)        // 41760 (8 parts x 512 f32 = 4096)
#define SM_AT (SM_SC + 4096)           // 45856
#define ATTN_SMEM ((SM_AT + 576) * 4)  // 185728 bytes

__global__ void __launch_bounds__(1024, 1)
attn_fused_k(const float* __restrict__ F, const float* __restrict__ Et,
             const __nv_bfloat16* __restrict__ qtg, __nv_bfloat16* __restrict__ Z) {
    extern __shared__ uint32_t smem_u[];
    uint32_t* fp_s = smem_u + SM_FP;
    uint32_t* qt_s = smem_u + SM_QT;
    float*    sc_s = (float*)(smem_u + SM_SC);
    __nv_bfloat16* at_s = (__nv_bfloat16*)(smem_u + SM_AT);

    const int tid = threadIdx.x;
    const int wid = tid >> 5, lane = tid & 31;

    if (tid < 288) ((uint32_t*)(at_s + 8 * 72))[tid] = 0;   // pad rows 8-15 (persist both iters)

    #pragma unroll 1
    for (int it = 0; it < 2; it++) {
        const int c = blockIdx.x + (it << 10);
        if (it) __syncthreads();

        // F/Et are external inputs: load BEFORE the PDL wait -> wave-1's DRAM-heavy
        // load overlaps the predecessor (gemm_fat) tail wave.
        {
            #pragma unroll
            for (int rr = 0; rr < 2; rr++) {
                const int row = (wid << 1) + rr;
                const float4* fF = (const float4*)F  + ((size_t)c * 64 + row) * 256;
                const float4* fE = (const float4*)Et + ((size_t)c * 64 + row) * 32;
                uint32_t* dst = fp_s + row * FPW;
                #pragma unroll
                for (int k2 = 0; k2 < 9; k2++) {
                    const int j = lane + (k2 << 5);
                    float4 v = (j < 256) ? fF[j] : fE[j - 256];
                    uint2 pk;
                    pk.x = packbf2(v.x, v.y);
                    pk.y = packbf2(v.z, v.w);
                    *(uint2*)(dst + j * 2) = pk;
                }
            }
        }
        if (it == 0) gdc_wait();   // qt produced by gemm_fat
        for (int i = tid; i < 8 * 288; i += 1024) {
            int row = i / 288, j = i - row * 288;
            uint2 v = ((const uint2*)(qtg + (size_t)c * (NH * DX) + row * DX))[j];
            *(uint2*)(qt_s + row * FPW + j * 2) = v;
        }
        __syncthreads();

        // prefetch chain: it0 covers own it1; it1 covers successor CTA's first tile
        {
            int c2 = -1;
            if (it == 0)                        c2 = blockIdx.x + 1024;
            else if (blockIdx.x + 148 < 1024)   c2 = blockIdx.x + 148;
            if (c2 >= 0) {
                const char* pf = (const char*)(F + (size_t)c2 * 64 * 1024);
                #pragma unroll
                for (int r = 0; r < 2; r++) prefetchL2(pf + (tid + (r << 10)) * 128);
                const char* pe = (const char*)(Et + (size_t)c2 * 64 * 128);
                if (tid < 256) prefetchL2(pe + tid * 128);
                const char* pq = (const char*)(qtg + (size_t)c2 * (NH * DX));
                if (tid >= 256 && tid < 400) prefetchL2(pq + (tid - 256) * 128);
            }
        }

        // phase 1: scores[64,8] = Fp @ qt^T ; 32 warps = 4 row-tiles x 8 K-parts
        {
            const int t = wid & 3;
            const int p = wid >> 2;
            const char* aP = (const char*)fp_s + (t * 16 + (lane & 15)) * 2320
                             + (lane >> 4) * 16 + p * 288;
            const char* bP = (const char*)qt_s + (lane & 7) * 2320
                             + (lane >> 4) * 16 + p * 288;
            float cacc[4] = {0.f, 0.f, 0.f, 0.f};
            #pragma unroll 3
            for (int kk = 0; kk < 9; kk++) {
                uint32_t a[4], b[4];
                ldm_x4(a, aP + kk * 32);
                ldm_x4(b, bP + kk * 32);
                mma16816(cacc, a, b[0], b[2]);
            }
            const int kr = t * 16 + (lane >> 2);
            const int h0 = (lane & 3) << 1;
            float* ps = sc_s + p * 512;
            ps[h0 * 64 + kr]           = cacc[0];
            ps[(h0 + 1) * 64 + kr]     = cacc[1];
            ps[h0 * 64 + kr + 8]       = cacc[2];
            ps[(h0 + 1) * 64 + kr + 8] = cacc[3];
        }
        __syncthreads();

        // phase 2: reduce 8 K-parts + softmax per head (warps 0-7)
        if (wid < 8) {
            const float sc = 0.08838834764831845f;
            float v0 = 0.f, v1 = 0.f;
            #pragma unroll
            for (int p = 0; p < 8; p++) {
                v0 += sc_s[p * 512 + wid * 64 + lane];
                v1 += sc_s[p * 512 + wid * 64 + lane + 32];
            }
            v0 *= sc; v1 *= sc;
            float m = fmaxf(v0, v1);
            #pragma unroll
            for (int o = 16; o; o >>= 1) m = fmaxf(m, __shfl_xor_sync(0xffffffffu, m, o));
            float e0 = __expf(v0 - m), e1 = __expf(v1 - m);
            float s = e0 + e1;
            #pragma unroll
            for (int o = 16; o; o >>= 1) s += __shfl_xor_sync(0xffffffffu, s, o);
            float inv = 1.f / s;
            at_s[wid * 72 + lane]      = __float2bfloat16(e0 * inv);
            at_s[wid * 72 + lane + 32] = __float2bfloat16(e1 * inv);
        }
        __syncthreads();

        // phase 3: z[8,1152] = attn @ Fp ; 32 warps over 72 x-tiles
        {
            uint32_t afr[4][4];
            const char* aP = (const char*)at_s + (lane & 15) * 144 + (lane >> 4) * 16;
            #pragma unroll
            for (int kk = 0; kk < 4; kk++) ldm_x4(afr[kk], aP + kk * 32);

            const int brow = (lane & 7) + ((lane >> 3) & 1) * 8;
            const int bcol = (lane >> 4) * 8;
            for (int xt = wid; xt < 72; xt += 32) {
                const int x0 = xt * 16;
                const char* bP = (const char*)fp_s + brow * 2320 + (x0 + bcol) * 2;
                float c0[4] = {0.f, 0.f, 0.f, 0.f}, c1[4] = {0.f, 0.f, 0.f, 0.f};
                #pragma unroll
                for (int kk = 0; kk < 4; kk++) {
                    uint32_t b[4];
                    ldm_x4t(b, bP + kk * 16 * 2320);
                    mma16816(c0, afr[kk], b[0], b[1]);
                    mma16816(c1, afr[kk], b[2], b[3]);
                }
                const int h = lane >> 2, xo = (lane & 3);
                uint32_t* zo = (uint32_t*)(Z + (size_t)c * (NH * DX) + h * DX + x0);
                zo[xo]     = packbf2(c0[0], c0[1]);
                zo[xo + 4] = packbf2(c1[0], c1[1]);
            }
        }
    }
}

// ---------------- finalize: out = U / max(||U||, eps) ----------------
__global__ void __launch_bounds__(256)
finalize_k(const float* __restrict__ U, float* __restrict__ out) {
    gdc_wait();
    const int c = blockIdx.x, tid = threadIdx.x;
    const int wid = tid >> 5, lane = tid & 31;
    __shared__ float sred[8];
    float u[4]; float ss = 0.f;
    #pragma unroll
    for (int i = 0; i < 4; i++) {
        u[i] = U[(size_t)c * DD + i * 256 + tid];
        ss += u[i] * u[i];
    }
    #pragma unroll
    for (int o = 16; o; o >>= 1) ss += __shfl_xor_sync(0xffffffffu, ss, o);
    if (lane == 0) sred[wid] = ss;
    __syncthreads();
    float tot = 0.f;
    #pragma unroll
    for (int h = 0; h < 8; h++) tot += sred[h];
    float inv = 1.f / fmaxf(sqrtf(tot), 1e-12f);
    #pragma unroll
    for (int i = 0; i < 4; i++)
        out[(size_t)c * DD + i * 256 + tid] = u[i] * inv;
}

// ---------------- launch ----------------
template <typename K, typename... Args>
static void launch_pdl(K kern, dim3 grid, dim3 block, size_t smem, Args... args) {
    cudaLaunchConfig_t cfg = {};
    cfg.gridDim = grid;
    cfg.blockDim = block;
    cfg.dynamicSmemBytes = smem;
    cudaLaunchAttribute attr[1];
    attr[0].id = cudaLaunchAttributeProgrammaticStreamSerialization;
    attr[0].val.programmaticStreamSerializationAllowed = 1;
    cfg.attrs = attr;
    cfg.numAttrs = 1;
    cudaLaunchKernelEx(&cfg, kern, args...);
}

extern "C" void kernel_launch(void* const* d_in, const int* in_sizes, int n_in,
                              void* d_out, int out_size) {
    const float* w   = (const float*)d_in[0];
    const float* F   = (const float*)d_in[1];
    const float* Et  = (const float*)d_in[2];
    const float* fC  = (const float*)d_in[3];
    const float* W1  = (const float*)d_in[4];
    const float* W2  = (const float*)d_in[5];
    const float* Wv  = (const float*)d_in[6];
    const float* Wf  = (const float*)d_in[7];
    // alpha (d_in[8]) cancels in softmax — unused
    const float* beta = (const float*)d_in[9];
    const float* g1w = (const float*)d_in[10];
    const float* g1b = (const float*)d_in[11];
    const float* g2w = (const float*)d_in[12];
    const float* g2b = (const float*)d_in[13];
    float* out = (float*)d_out;

    __nv_bfloat16 *Wc, *wfm, *QH, *W1t, *Wvb, *g2wb, *qt, *Z;
    float *gbuf, *U;
    cudaGetSymbolAddress((void**)&Wc,   g_Wc);
    cudaGetSymbolAddress((void**)&wfm,  g_wfm);
    cudaGetSymbolAddress((void**)&QH,   g_QH);
    cudaGetSymbolAddress((void**)&W1t,  g_W1t);
    cudaGetSymbolAddress((void**)&Wvb,  g_Wvb);
    cudaGetSymbolAddress((void**)&g2wb, g_g2wb);
    cudaGetSymbolAddress((void**)&qt,   g_qt);
    cudaGetSymbolAddress((void**)&Z,    g_Z);
    cudaGetSymbolAddress((void**)&gbuf, g_g);
    cudaGetSymbolAddress((void**)&U,    g_U);

    cudaFuncSetAttribute(attn_fused_k, cudaFuncAttributeMaxDynamicSharedMemorySize, ATTN_SMEM);
    cudaFuncSetAttribute(gemm_qh_k,   cudaFuncAttributeMaxDynamicSharedMemorySize, GEMM_SMEM);
    cudaFuncSetAttribute(gemm_fat_k,  cudaFuncAttributeMaxDynamicSharedMemorySize, FAT_SMEM);
    cudaFuncSetAttribute(gemm_gate_k, cudaFuncAttributeMaxDynamicSharedMemorySize, GEMM_SMEM);

    prep_fat_k<<<PREP_TOTAL / 256, 256>>>(w, Et, fC, W1, W2, Wv, Wf, beta, g1w, g2w,
                                          Wc, wfm, W1t, Wvb, g2wb);
    launch_pdl(gemm_qh_k, dim3(16, 16), dim3(256), GEMM_SMEM, wfm, Wc, QH, g1b);
    launch_pdl(gemm_fat_k, dim3(256), dim3(256), FAT_SMEM, QH, W1t, qt, g2wb, gbuf, g2b);
    launch_pdl(attn_fused_k, dim3(1024), dim3(1024), (size_t)ATTN_SMEM, F, Et, qt, Z);
    launch_pdl(gemm_gate_k, dim3(1, 16, 8), dim3(256), GEMM_SMEM, Z, Wvb, U, gbuf, w);
    launch_pdl(finalize_k, dim3(CC), dim3(256), (size_t)0, U, out);
}